// round 9
// baseline (speedup 1.0000x reference)
#include <cuda_runtime.h>
#include <cuda_fp16.h>
#include <math.h>
#include <stdint.h>

#define T_TOK 1024
#define H_DIM 1024
#define E_NUM 32
#define I_DIM 512
#define IS_DIM 2048
#define NGROUP 8
#define GSIZE 4
#define TOPKG 4
#define TOPK 8
#define RSCALE 2.5f

// Scratch: activations stored as fp16
__device__ __half g_xh[(size_t)T_TOK * H_DIM];
__device__ __half g_act[(size_t)E_NUM * T_TOK * I_DIM];
__device__ __half g_sact[(size_t)T_TOK * IS_DIM];
__device__ float g_dact[(size_t)E_NUM * T_TOK * H_DIM];   // routed down staging
__device__ float g_sds[4][(size_t)T_TOK * H_DIM];         // shared split-K staging
__device__ int   g_cnt[E_NUM];
__device__ int   g_tok[E_NUM * T_TOK];
__device__ float g_wgt[E_NUM * T_TOK];
__device__ int   g_pos[T_TOK * TOPK];

__device__ __forceinline__ float silu_f(float v) { return v / (1.f + expf(-v)); }

__device__ __forceinline__ uint32_t h2pack(float a, float b) {
    __half2 h = __floats2half2_rn(a, b);
    return *reinterpret_cast<uint32_t*>(&h);
}

__device__ __forceinline__ uint32_t smem_u32(const void* p) {
    uint32_t a;
    asm("{ .reg .u64 t; cvta.to.shared.u64 t, %1; cvt.u32.u64 %0, t; }" : "=r"(a) : "l"(p));
    return a;
}

__device__ __forceinline__ void mma_f16(float* c,
                                        uint32_t a0, uint32_t a1, uint32_t a2, uint32_t a3,
                                        uint32_t b0, uint32_t b1)
{
    asm volatile(
        "mma.sync.aligned.m16n8k16.row.col.f32.f16.f16.f32 "
        "{%0,%1,%2,%3}, {%4,%5,%6,%7}, {%8,%9}, {%0,%1,%2,%3};\n"
        : "+f"(c[0]), "+f"(c[1]), "+f"(c[2]), "+f"(c[3])
        : "r"(a0), "r"(a1), "r"(a2), "r"(a3), "r"(b0), "r"(b1));
}

#define CP16(dst, src, sz) \
    asm volatile("cp.async.cg.shared.global [%0], [%1], 16, %2;" \
                 :: "r"(dst), "l"(src), "r"(sz) : "memory")
#define CP_COMMIT() asm volatile("cp.async.commit_group;" ::: "memory")
#define CP_WAIT1()  asm volatile("cp.async.wait_group 1;" ::: "memory")

// convert X -> fp16 once; block 0 zeroes expert counters
__global__ void k_xtf(const float* __restrict__ x) {
    if (blockIdx.x == 0 && threadIdx.x < E_NUM) g_cnt[threadIdx.x] = 0;
    size_t i = (size_t)blockIdx.x * 256 + threadIdx.x;
    float4 v = ((const float4*)x)[i];
    ((uint2*)g_xh)[i] = make_uint2(h2pack(v.x, v.y), h2pack(v.z, v.w));
}

// ---------------------------------------------------------------------------
// Gate GEMV + DeepseekV3 noaux_tc routing + per-expert gather
// ---------------------------------------------------------------------------
__global__ __launch_bounds__(256) void k_gate_route(
    const float* __restrict__ x,
    const float* __restrict__ gate_w,
    const float* __restrict__ e_bias)
{
    __shared__ float s_logit[E_NUM];
    const int t = blockIdx.x;
    const int warp = threadIdx.x >> 5, lane = threadIdx.x & 31;
    const float* xr = x + (size_t)t * H_DIM;
    for (int e = warp; e < E_NUM; e += 8) {
        const float* gw = gate_w + (size_t)e * H_DIM;
        float s = 0.f;
        for (int k = lane; k < H_DIM; k += 32) s += xr[k] * gw[k];
        #pragma unroll
        for (int o = 16; o; o >>= 1) s += __shfl_xor_sync(0xffffffffu, s, o);
        if (lane == 0) s_logit[e] = s;
    }
    __syncthreads();
    if (threadIdx.x != 0) return;

    float scores[E_NUM], swb[E_NUM];
    for (int e = 0; e < E_NUM; e++) {
        float sc = 1.f / (1.f + expf(-s_logit[e]));
        scores[e] = sc;
        swb[e] = sc + e_bias[e];
    }
    float gs[NGROUP];
    for (int g = 0; g < NGROUP; g++) {
        float m1 = -1e30f, m2 = -1e30f;
        for (int j = 0; j < GSIZE; j++) {
            float v = swb[g * GSIZE + j];
            if (v > m1) { m2 = m1; m1 = v; }
            else if (v > m2) m2 = v;
        }
        gs[g] = m1 + m2;
    }
    bool gsel[NGROUP] = {false};
    for (int it = 0; it < TOPKG; it++) {
        int bi = 0; float bv = -1e30f;
        for (int g = 0; g < NGROUP; g++)
            if (!gsel[g] && gs[g] > bv) { bv = gs[g]; bi = g; }
        gsel[bi] = true;
    }
    float val[E_NUM];
    for (int e = 0; e < E_NUM; e++) val[e] = gsel[e / GSIZE] ? swb[e] : 0.f;
    bool taken[E_NUM] = {false};
    int sel[TOPK];
    float denom = 0.f;
    for (int it = 0; it < TOPK; it++) {
        int bi = 0; float bv = -1e30f;
        for (int e = 0; e < E_NUM; e++)
            if (!taken[e] && val[e] > bv) { bv = val[e]; bi = e; }
        taken[bi] = true; sel[it] = bi; denom += scores[bi];
    }
    float inv = RSCALE / (denom + 1e-20f);
    for (int it = 0; it < TOPK; it++) {
        int e = sel[it];
        int slot = atomicAdd(&g_cnt[e], 1);
        g_tok[e * T_TOK + slot] = t;
        g_wgt[e * T_TOK + slot] = scores[e] * inv;
        g_pos[t * TOPK + it] = e * T_TOK + slot;
    }
}

// ---------------------------------------------------------------------------
// Per-stage smem (32-bit words), all rows stride 12 (8 k-words fp16 + 4 pad):
//   A: 128 rows x 12 = 1536 w  (fragment reads 12*grp+tg: conflict-free)
//   B: [n][k] rows x 12        (dual: 2x64 rows; down: 128 rows) = 1536 w
// Stage = 3072 words = 12288 B; 3 stages = 36864 B dynamic smem.
// ---------------------------------------------------------------------------
#define STAGE_W 3072
#define STAGE_B 12288
#define SMEM_BYTES (3 * STAGE_B)

// ---------------------------------------------------------------------------
// Dual fp16 MMA GEMM: act = silu(X@Wg)*(X@Wu) [* combine]  (fp16 in, fp32 acc)
// Block 128x64, BK=16, 4 warps (2m x 2n), warp 64x32 dual.
// A: cp.async fp16. B: LDG fp32 (coalesced along n) -> cvt -> STS [n][k].
// z<32: routed expert z. z>=32: shared N-slice (z-32)*512.
// ---------------------------------------------------------------------------
__global__ __launch_bounds__(128, 3)
void k_dual(const float* __restrict__ w_gate,
            const float* __restrict__ w_up,
            const float* __restrict__ ws_gate,
            const float* __restrict__ ws_up)
{
    extern __shared__ uint32_t sm[];
    const int z = blockIdx.z;
    const bool routed = z < E_NUM;
    const int e = routed ? z : 0;
    const int M = routed ? g_cnt[e] : T_TOK;
    const int m0 = blockIdx.y * 128;
    if (m0 >= M) return;
    const int NS = routed ? I_DIM : IS_DIM;
    const int n0 = routed ? blockIdx.x * 64
                          : (z - E_NUM) * 512 + blockIdx.x * 64;
    const float* __restrict__ Wg = routed ? w_gate + (size_t)e * H_DIM * I_DIM : ws_gate;
    const float* __restrict__ Wu = routed ? w_up   + (size_t)e * H_DIM * I_DIM : ws_up;
    __half* __restrict__ Act = routed ? g_act + (size_t)e * T_TOK * I_DIM : g_sact;

    const uint32_t sb = smem_u32(sm);
    const int tid = threadIdx.x;
    const int warp = tid >> 5, lane = tid & 31;
    const int wm = warp & 1, wn = warp >> 1;
    const int grp = lane >> 2, tg = lane & 3;

    // A cp.async: 128 rows x 16 halves = 256 16B-units, 2/thread
    const __half* aSrc[2];
    uint32_t aDst[2], aSz[2];
    #pragma unroll
    for (int u = 0; u < 2; u++) {
        int idx = tid + u * 128;
        int am = idx >> 1, ak = idx & 1;
        int gm = m0 + am;
        bool ok = gm < M;
        int srow = ok ? (routed ? g_tok[e * T_TOK + gm] : gm) : 0;
        aSrc[u] = g_xh + (size_t)srow * H_DIM + ak * 8;
        aDst[u] = (uint32_t)(am * 48 + ak * 16);
        aSz[u] = ok ? 16u : 0u;
    }
    // B: per matrix 64 n x 4 kg = 256 units, 2/thread/matrix
    const float* gSrc[2];
    const float* uSrc[2];
    uint32_t bOff[2];
    #pragma unroll
    for (int u = 0; u < 2; u++) {
        int idx = tid + u * 128;
        int n = idx & 63, kg = idx >> 6;
        gSrc[u] = Wg + (size_t)(kg * 4) * NS + n0 + n;
        uSrc[u] = Wu + (size_t)(kg * 4) * NS + n0 + n;
        bOff[u] = (uint32_t)(n * 48 + kg * 8);
    }

    // fragment word offsets
    int aw[4];
    #pragma unroll
    for (int mi = 0; mi < 4; mi++)
        aw[mi] = (wm * 64 + mi * 16 + grp) * 12 + tg;
    int bwg[4];
    #pragma unroll
    for (int ni = 0; ni < 4; ni++)
        bwg[ni] = 1536 + (wn * 32 + ni * 8 + grp) * 12 + tg;

    const int NC = H_DIM / 16;  // 64
    // prologue: stages 0, 1 (A via cp.async; B via LDG+STS)
    #pragma unroll
    for (int c = 0; c < 2; c++) {
        uint32_t st = sb + c * STAGE_B;
        #pragma unroll
        for (int u = 0; u < 2; u++) CP16(st + aDst[u], aSrc[u] + c * 16, aSz[u]);
        CP_COMMIT();
        uint32_t* S = sm + c * STAGE_W;
        #pragma unroll
        for (int u = 0; u < 2; u++) {
            float f0 = gSrc[u][(size_t)(c * 16 + 0) * NS];
            float f1 = gSrc[u][(size_t)(c * 16 + 1) * NS];
            float f2 = gSrc[u][(size_t)(c * 16 + 2) * NS];
            float f3 = gSrc[u][(size_t)(c * 16 + 3) * NS];
            *(uint2*)((char*)(S + 1536) + bOff[u]) = make_uint2(h2pack(f0, f1), h2pack(f2, f3));
            f0 = uSrc[u][(size_t)(c * 16 + 0) * NS];
            f1 = uSrc[u][(size_t)(c * 16 + 1) * NS];
            f2 = uSrc[u][(size_t)(c * 16 + 2) * NS];
            f3 = uSrc[u][(size_t)(c * 16 + 3) * NS];
            *(uint2*)((char*)(S + 2304) + bOff[u]) = make_uint2(h2pack(f0, f1), h2pack(f2, f3));
        }
    }

    float cg[4][4][4], cu[4][4][4];
    #pragma unroll
    for (int mi = 0; mi < 4; mi++)
        #pragma unroll
        for (int ni = 0; ni < 4; ni++)
            #pragma unroll
            for (int q = 0; q < 4; q++) { cg[mi][ni][q] = 0.f; cu[mi][ni][q] = 0.f; }

    for (int c = 0; c < NC; c++) {
        CP_WAIT1();
        __syncthreads();
        // issue A cp.async + B LDGs for stage c+2 (STS after MMA hides LDG latency)
        float fg[2][4], fu[2][4];
        const bool more = (c + 2) < NC;
        if (more) {
            int c2 = c + 2;
            uint32_t st = sb + (c2 % 3) * STAGE_B;
            #pragma unroll
            for (int u = 0; u < 2; u++) CP16(st + aDst[u], aSrc[u] + c2 * 16, aSz[u]);
            #pragma unroll
            for (int u = 0; u < 2; u++) {
                #pragma unroll
                for (int j = 0; j < 4; j++) {
                    fg[u][j] = gSrc[u][(size_t)(c2 * 16 + j) * NS];
                    fu[u][j] = uSrc[u][(size_t)(c2 * 16 + j) * NS];
                }
            }
        }
        CP_COMMIT();
        const uint32_t* S = sm + (c % 3) * STAGE_W;
        uint32_t af[4][4];
        #pragma unroll
        for (int mi = 0; mi < 4; mi++) {
            af[mi][0] = S[aw[mi]];
            af[mi][1] = S[aw[mi] + 96];
            af[mi][2] = S[aw[mi] + 4];
            af[mi][3] = S[aw[mi] + 100];
        }
        #pragma unroll
        for (int ni = 0; ni < 4; ni++) {
            uint32_t bg0 = S[bwg[ni]];
            uint32_t bg1 = S[bwg[ni] + 4];
            uint32_t bu0 = S[bwg[ni] + 768];
            uint32_t bu1 = S[bwg[ni] + 772];
            #pragma unroll
            for (int mi = 0; mi < 4; mi++) {
                mma_f16(cg[mi][ni], af[mi][0], af[mi][1], af[mi][2], af[mi][3], bg0, bg1);
                mma_f16(cu[mi][ni], af[mi][0], af[mi][1], af[mi][2], af[mi][3], bu0, bu1);
            }
        }
        if (more) {
            uint32_t* D = sm + ((c + 2) % 3) * STAGE_W;
            #pragma unroll
            for (int u = 0; u < 2; u++) {
                *(uint2*)((char*)(D + 1536) + bOff[u]) =
                    make_uint2(h2pack(fg[u][0], fg[u][1]), h2pack(fg[u][2], fg[u][3]));
                *(uint2*)((char*)(D + 2304) + bOff[u]) =
                    make_uint2(h2pack(fu[u][0], fu[u][1]), h2pack(fu[u][2], fu[u][3]));
            }
        }
    }

    // epilogue: silu(g)*u (* wgt), store fp16
    #pragma unroll
    for (int mi = 0; mi < 4; mi++) {
        int r0 = m0 + wm * 64 + mi * 16 + grp;
        int r1 = r0 + 8;
        float w0 = 1.f, w1 = 1.f;
        if (routed) {
            if (r0 < M) w0 = g_wgt[e * T_TOK + r0];
            if (r1 < M) w1 = g_wgt[e * T_TOK + r1];
        }
        #pragma unroll
        for (int ni = 0; ni < 4; ni++) {
            int col = n0 + wn * 32 + ni * 8 + tg * 2;
            if (r0 < M) {
                uint32_t v = h2pack(silu_f(cg[mi][ni][0]) * cu[mi][ni][0] * w0,
                                    silu_f(cg[mi][ni][1]) * cu[mi][ni][1] * w0);
                *(uint32_t*)(Act + (size_t)r0 * NS + col) = v;
            }
            if (r1 < M) {
                uint32_t v = h2pack(silu_f(cg[mi][ni][2]) * cu[mi][ni][2] * w1,
                                    silu_f(cg[mi][ni][3]) * cu[mi][ni][3] * w1);
                *(uint32_t*)(Act + (size_t)r1 * NS + col) = v;
            }
        }
    }
}

// ---------------------------------------------------------------------------
// Down-proj fp16 MMA: staged plain stores (no atomics)
// Block 128x128, BK=16, 4 warps (2m x 2n), warp 64x64.
// z<32: routed expert z -> g_dact. z>=32: shared K-slice -> g_sds.
// ---------------------------------------------------------------------------
__global__ __launch_bounds__(128, 3)
void k_down(const float* __restrict__ w_down,
            const float* __restrict__ ws_down)
{
    extern __shared__ uint32_t sm[];
    const int z = blockIdx.z;
    const bool routed = z < E_NUM;
    const int e = routed ? z : 0;
    const int M = routed ? g_cnt[e] : T_TOK;
    const int m0 = blockIdx.y * 128;
    if (m0 >= M) return;
    const int n0 = blockIdx.x * 128;
    const int koff = routed ? 0 : (z - E_NUM) * 512;
    const __half* __restrict__ A = routed ? g_act + (size_t)e * T_TOK * I_DIM : g_sact;
    const int AS = routed ? I_DIM : IS_DIM;
    const float* __restrict__ B = routed ? w_down + (size_t)e * I_DIM * H_DIM
                                         : ws_down + (size_t)koff * H_DIM;
    float* __restrict__ Dst = routed ? g_dact + (size_t)e * T_TOK * H_DIM
                                     : g_sds[z - E_NUM];
    const int N = H_DIM;

    const uint32_t sb = smem_u32(sm);
    const int tid = threadIdx.x;
    const int warp = tid >> 5, lane = tid & 31;
    const int wm = warp & 1, wn = warp >> 1;
    const int grp = lane >> 2, tg = lane & 3;

    // A cp.async: 256 16B-units, 2/thread
    const __half* aSrc[2];
    uint32_t aDst[2], aSz[2];
    #pragma unroll
    for (int u = 0; u < 2; u++) {
        int idx = tid + u * 128;
        int am = idx >> 1, ak = idx & 1;
        int gm = m0 + am;
        bool ok = gm < M;
        aSrc[u] = A + (size_t)(ok ? gm : 0) * AS + koff + ak * 8;
        aDst[u] = (uint32_t)(am * 48 + ak * 16);
        aSz[u] = ok ? 16u : 0u;
    }
    // B: 128 n x 4 kg = 512 units, 4/thread
    const float* bSrc[4];
    uint32_t bOff[4];
    #pragma unroll
    for (int u = 0; u < 4; u++) {
        int idx = tid + u * 128;
        int n = idx & 127, kg = idx >> 7;
        bSrc[u] = B + (size_t)(kg * 4) * N + n0 + n;
        bOff[u] = (uint32_t)(n * 48 + kg * 8);
    }

    int aw[4];
    #pragma unroll
    for (int mi = 0; mi < 4; mi++)
        aw[mi] = (wm * 64 + mi * 16 + grp) * 12 + tg;
    int bw[8];
    #pragma unroll
    for (int ni = 0; ni < 8; ni++)
        bw[ni] = 1536 + (wn * 64 + ni * 8 + grp) * 12 + tg;

    const int NC = 512 / 16;  // 32
    #pragma unroll
    for (int c = 0; c < 2; c++) {
        uint32_t st = sb + c * STAGE_B;
        #pragma unroll
        for (int u = 0; u < 2; u++) CP16(st + aDst[u], aSrc[u] + c * 16, aSz[u]);
        CP_COMMIT();
        uint32_t* S = sm + c * STAGE_W;
        #pragma unroll
        for (int u = 0; u < 4; u++) {
            float f0 = bSrc[u][(size_t)(c * 16 + 0) * N];
            float f1 = bSrc[u][(size_t)(c * 16 + 1) * N];
            float f2 = bSrc[u][(size_t)(c * 16 + 2) * N];
            float f3 = bSrc[u][(size_t)(c * 16 + 3) * N];
            *(uint2*)((char*)(S + 1536) + bOff[u]) = make_uint2(h2pack(f0, f1), h2pack(f2, f3));
        }
    }

    float acc[4][8][4];
    #pragma unroll
    for (int mi = 0; mi < 4; mi++)
        #pragma unroll
        for (int ni = 0; ni < 8; ni++)
            #pragma unroll
            for (int q = 0; q < 4; q++) acc[mi][ni][q] = 0.f;

    for (int c = 0; c < NC; c++) {
        CP_WAIT1();
        __syncthreads();
        float fb[4][4];
        const bool more = (c + 2) < NC;
        if (more) {
            int c2 = c + 2;
            uint32_t st = sb + (c2 % 3) * STAGE_B;
            #pragma unroll
            for (int u = 0; u < 2; u++) CP16(st + aDst[u], aSrc[u] + c2 * 16, aSz[u]);
            #pragma unroll
            for (int u = 0; u < 4; u++)
                #pragma unroll
                for (int j = 0; j < 4; j++)
                    fb[u][j] = bSrc[u][(size_t)(c2 * 16 + j) * N];
        }
        CP_COMMIT();
        const uint32_t* S = sm + (c % 3) * STAGE_W;
        uint32_t af[4][4];
        #pragma unroll
        for (int mi = 0; mi < 4; mi++) {
            af[mi][0] = S[aw[mi]];
            af[mi][1] = S[aw[mi] + 96];
            af[mi][2] = S[aw[mi] + 4];
            af[mi][3] = S[aw[mi] + 100];
        }
        #pragma unroll
        for (int ni = 0; ni < 8; ni++) {
            uint32_t b0 = S[bw[ni]];
            uint32_t b1 = S[bw[ni] + 4];
            #pragma unroll
            for (int mi = 0; mi < 4; mi++)
                mma_f16(acc[mi][ni], af[mi][0], af[mi][1], af[mi][2], af[mi][3], b0, b1);
        }
        if (more) {
            uint32_t* D = sm + ((c + 2) % 3) * STAGE_W;
            #pragma unroll
            for (int u = 0; u < 4; u++)
                *(uint2*)((char*)(D + 1536) + bOff[u]) =
                    make_uint2(h2pack(fb[u][0], fb[u][1]), h2pack(fb[u][2], fb[u][3]));
        }
    }

    // epilogue: plain stores to staging
    #pragma unroll
    for (int mi = 0; mi < 4; mi++) {
        int r0 = m0 + wm * 64 + mi * 16 + grp;
        int r1 = r0 + 8;
        bool ok0 = r0 < M, ok1 = r1 < M;
        #pragma unroll
        for (int ni = 0; ni < 8; ni++) {
            int col = n0 + wn * 64 + ni * 8 + tg * 2;
            if (ok0) {
                float2 v = make_float2(acc[mi][ni][0], acc[mi][ni][1]);
                *(float2*)(Dst + (size_t)r0 * N + col) = v;
            }
            if (ok1) {
                float2 v = make_float2(acc[mi][ni][2], acc[mi][ni][3]);
                *(float2*)(Dst + (size_t)r1 * N + col) = v;
            }
        }
    }
}

// ---------------------------------------------------------------------------
// Final gather-reduce: out[t] = sum_{i<8} g_dact[pos_i] + sum_{s<4} g_sds[s][t]
// ---------------------------------------------------------------------------
__global__ __launch_bounds__(256) void k_reduce(float* __restrict__ out) {
    __shared__ int pos[TOPK];
    const int t = blockIdx.x;
    if (threadIdx.x < TOPK) pos[threadIdx.x] = g_pos[t * TOPK + threadIdx.x];
    __syncthreads();
    const int h = threadIdx.x * 4;
    float4 s = *(const float4*)(&g_sds[0][(size_t)t * H_DIM + h]);
    #pragma unroll
    for (int q = 1; q < 4; q++) {
        float4 v = *(const float4*)(&g_sds[q][(size_t)t * H_DIM + h]);
        s.x += v.x; s.y += v.y; s.z += v.z; s.w += v.w;
    }
    #pragma unroll
    for (int i = 0; i < TOPK; i++) {
        float4 v = *(const float4*)(g_dact + (size_t)pos[i] * H_DIM + h);
        s.x += v.x; s.y += v.y; s.z += v.z; s.w += v.w;
    }
    *(float4*)(out + (size_t)t * H_DIM + h) = s;
}

// ---------------------------------------------------------------------------
extern "C" void kernel_launch(void* const* d_in, const int* in_sizes, int n_in,
                              void* d_out, int out_size)
{
    const float* x       = (const float*)d_in[0];
    const float* gate_w  = (const float*)d_in[1];
    const float* e_bias  = (const float*)d_in[2];
    const float* w_gate  = (const float*)d_in[3];
    const float* w_up    = (const float*)d_in[4];
    const float* w_down  = (const float*)d_in[5];
    const float* ws_gate = (const float*)d_in[6];
    const float* ws_up   = (const float*)d_in[7];
    const float* ws_down = (const float*)d_in[8];
    float* out = (float*)d_out;

    static bool attr_done = false;
    if (!attr_done) {
        cudaFuncSetAttribute(k_dual, cudaFuncAttributeMaxDynamicSharedMemorySize, SMEM_BYTES);
        cudaFuncSetAttribute(k_down, cudaFuncAttributeMaxDynamicSharedMemorySize, SMEM_BYTES);
        attr_done = true;
    }

    k_xtf<<<(T_TOK * H_DIM) / (256 * 4), 256>>>(x);
    k_gate_route<<<T_TOK, 256>>>(x, gate_w, e_bias);
    k_dual<<<dim3(8, 8, E_NUM + 4), 128, SMEM_BYTES>>>(w_gate, w_up, ws_gate, ws_up);
    k_down<<<dim3(8, 8, E_NUM + 4), 128, SMEM_BYTES>>>(w_down, ws_down);
    k_reduce<<<T_TOK, 256>>>(out);
}

// round 10
// speedup vs baseline: 1.5979x; 1.5979x over previous
#include <cuda_runtime.h>
#include <cuda_fp16.h>
#include <math.h>
#include <stdint.h>

#define T_TOK 1024
#define H_DIM 1024
#define E_NUM 32
#define I_DIM 512
#define IS_DIM 2048
#define NGROUP 8
#define GSIZE 4
#define TOPKG 4
#define TOPK 8
#define RSCALE 2.5f

// Scratch: activations stored as fp16
__device__ __half g_xh[(size_t)T_TOK * H_DIM];
__device__ __half g_act[(size_t)E_NUM * T_TOK * I_DIM];
__device__ __half g_sact[(size_t)T_TOK * IS_DIM];
__device__ float g_dact[(size_t)E_NUM * T_TOK * H_DIM];   // routed down staging
__device__ float g_sds[4][(size_t)T_TOK * H_DIM];         // shared split-K staging
__device__ int   g_cnt[E_NUM];
__device__ int   g_tok[E_NUM * T_TOK];
__device__ float g_wgt[E_NUM * T_TOK];
__device__ int   g_pos[T_TOK * TOPK];

__device__ __forceinline__ float silu_f(float v) { return v / (1.f + expf(-v)); }

__device__ __forceinline__ uint32_t h2pack(float a, float b) {
    __half2 h = __floats2half2_rn(a, b);
    return *reinterpret_cast<uint32_t*>(&h);
}

__device__ __forceinline__ uint32_t smem_u32(const void* p) {
    uint32_t a;
    asm("{ .reg .u64 t; cvta.to.shared.u64 t, %1; cvt.u32.u64 %0, t; }" : "=r"(a) : "l"(p));
    return a;
}

__device__ __forceinline__ void mma_f16(float* c,
                                        uint32_t a0, uint32_t a1, uint32_t a2, uint32_t a3,
                                        uint32_t b0, uint32_t b1)
{
    asm volatile(
        "mma.sync.aligned.m16n8k16.row.col.f32.f16.f16.f32 "
        "{%0,%1,%2,%3}, {%4,%5,%6,%7}, {%8,%9}, {%0,%1,%2,%3};\n"
        : "+f"(c[0]), "+f"(c[1]), "+f"(c[2]), "+f"(c[3])
        : "r"(a0), "r"(a1), "r"(a2), "r"(a3), "r"(b0), "r"(b1));
}

#define CP16(dst, src, sz) \
    asm volatile("cp.async.cg.shared.global [%0], [%1], 16, %2;" \
                 :: "r"(dst), "l"(src), "r"(sz) : "memory")
#define CP_COMMIT() asm volatile("cp.async.commit_group;" ::: "memory")
#define CP_WAIT1()  asm volatile("cp.async.wait_group 1;" ::: "memory")

// convert X -> fp16 once; block 0 zeroes expert counters
__global__ void k_xtf(const float* __restrict__ x) {
    if (blockIdx.x == 0 && threadIdx.x < E_NUM) g_cnt[threadIdx.x] = 0;
    size_t i = (size_t)blockIdx.x * 256 + threadIdx.x;
    float4 v = ((const float4*)x)[i];
    ((uint2*)g_xh)[i] = make_uint2(h2pack(v.x, v.y), h2pack(v.z, v.w));
}

// ---------------------------------------------------------------------------
// Gate GEMV + DeepseekV3 noaux_tc routing + per-expert gather
// ---------------------------------------------------------------------------
__global__ __launch_bounds__(256) void k_gate_route(
    const float* __restrict__ x,
    const float* __restrict__ gate_w,
    const float* __restrict__ e_bias)
{
    __shared__ float s_logit[E_NUM];
    const int t = blockIdx.x;
    const int warp = threadIdx.x >> 5, lane = threadIdx.x & 31;
    const float* xr = x + (size_t)t * H_DIM;
    for (int e = warp; e < E_NUM; e += 8) {
        const float* gw = gate_w + (size_t)e * H_DIM;
        float s = 0.f;
        for (int k = lane; k < H_DIM; k += 32) s += xr[k] * gw[k];
        #pragma unroll
        for (int o = 16; o; o >>= 1) s += __shfl_xor_sync(0xffffffffu, s, o);
        if (lane == 0) s_logit[e] = s;
    }
    __syncthreads();
    if (threadIdx.x != 0) return;

    float scores[E_NUM], swb[E_NUM];
    for (int e = 0; e < E_NUM; e++) {
        float sc = 1.f / (1.f + expf(-s_logit[e]));
        scores[e] = sc;
        swb[e] = sc + e_bias[e];
    }
    float gs[NGROUP];
    for (int g = 0; g < NGROUP; g++) {
        float m1 = -1e30f, m2 = -1e30f;
        for (int j = 0; j < GSIZE; j++) {
            float v = swb[g * GSIZE + j];
            if (v > m1) { m2 = m1; m1 = v; }
            else if (v > m2) m2 = v;
        }
        gs[g] = m1 + m2;
    }
    bool gsel[NGROUP] = {false};
    for (int it = 0; it < TOPKG; it++) {
        int bi = 0; float bv = -1e30f;
        for (int g = 0; g < NGROUP; g++)
            if (!gsel[g] && gs[g] > bv) { bv = gs[g]; bi = g; }
        gsel[bi] = true;
    }
    float val[E_NUM];
    for (int e = 0; e < E_NUM; e++) val[e] = gsel[e / GSIZE] ? swb[e] : 0.f;
    bool taken[E_NUM] = {false};
    int sel[TOPK];
    float denom = 0.f;
    for (int it = 0; it < TOPK; it++) {
        int bi = 0; float bv = -1e30f;
        for (int e = 0; e < E_NUM; e++)
            if (!taken[e] && val[e] > bv) { bv = val[e]; bi = e; }
        taken[bi] = true; sel[it] = bi; denom += scores[bi];
    }
    float inv = RSCALE / (denom + 1e-20f);
    for (int it = 0; it < TOPK; it++) {
        int e = sel[it];
        int slot = atomicAdd(&g_cnt[e], 1);
        g_tok[e * T_TOK + slot] = t;
        g_wgt[e * T_TOK + slot] = scores[e] * inv;
        g_pos[t * TOPK + it] = e * T_TOK + slot;
    }
}

// ---------------------------------------------------------------------------
// Per-stage smem (32-bit words):
//   A (fp16): 128 rows x 12 words (8 data + 4 pad) = 1536 w (bank-clean)
//   B (fp32): [k][n], 16 rows x rowW words, 16B-chunk swizzle
//             phys_chunk = bc ^ (((bk>>1)&3)<<1)
//   dual: rowW=64, two matrices (g @1536, u @2560) -> stage 3584 w
//   down: rowW=128, one matrix (@1536)            -> stage 3584 w
// Stage = 14336 B; 3 stages = 43008 B dynamic smem.
// ---------------------------------------------------------------------------
#define STAGE_W 3584
#define STAGE_B 14336
#define SMEM_BYTES (3 * STAGE_B)

// ---------------------------------------------------------------------------
// Dual fp16 MMA GEMM: act = silu(X@Wg)*(X@Wu) [* combine]  (fp32 acc)
// Block 128x64, BK=16, 4 warps (2m x 2n), warp 64x32 dual.
// A: cp.async fp16. B: cp.async fp32 -> cvt at fragment read.
// z<32: routed expert z. z>=32: shared N-slice (z-32)*512.
// ---------------------------------------------------------------------------
__global__ __launch_bounds__(128, 3)
void k_dual(const float* __restrict__ w_gate,
            const float* __restrict__ w_up,
            const float* __restrict__ ws_gate,
            const float* __restrict__ ws_up)
{
    extern __shared__ uint32_t sm[];
    const int z = blockIdx.z;
    const bool routed = z < E_NUM;
    const int e = routed ? z : 0;
    const int M = routed ? g_cnt[e] : T_TOK;
    const int m0 = blockIdx.y * 128;
    if (m0 >= M) return;
    const int NS = routed ? I_DIM : IS_DIM;
    const int n0 = routed ? blockIdx.x * 64
                          : (z - E_NUM) * 512 + blockIdx.x * 64;
    const float* __restrict__ Wg = routed ? w_gate + (size_t)e * H_DIM * I_DIM : ws_gate;
    const float* __restrict__ Wu = routed ? w_up   + (size_t)e * H_DIM * I_DIM : ws_up;
    __half* __restrict__ Act = routed ? g_act + (size_t)e * T_TOK * I_DIM : g_sact;

    const uint32_t sb = smem_u32(sm);
    const int tid = threadIdx.x;
    const int warp = tid >> 5, lane = tid & 31;
    const int wm = warp & 1, wn = warp >> 1;
    const int grp = lane >> 2, tg = lane & 3;

    // A cp.async: 128 rows x 16 halves = 256 16B-units, 2/thread
    const __half* aSrc[2];
    uint32_t aDst[2], aSz[2];
    #pragma unroll
    for (int u = 0; u < 2; u++) {
        int idx = tid + u * 128;
        int am = idx >> 1, ak = idx & 1;
        int gm = m0 + am;
        bool ok = gm < M;
        int srow = ok ? (routed ? g_tok[e * T_TOK + gm] : gm) : 0;
        aSrc[u] = g_xh + (size_t)srow * H_DIM + ak * 8;
        aDst[u] = (uint32_t)(am * 48 + ak * 16);
        aSz[u] = ok ? 16u : 0u;
    }
    // B cp.async (fp32): per matrix 16 rows x 16 chunks = 256 units, 2/thr/mat
    const float* gSrc[2];
    const float* uSrc[2];
    uint32_t bDst[2];
    #pragma unroll
    for (int u = 0; u < 2; u++) {
        int idx = tid + u * 128;
        int bk = idx >> 4, bc = idx & 15;
        int cph = bc ^ (((bk >> 1) & 3) << 1);
        gSrc[u] = Wg + (size_t)bk * NS + n0 + bc * 4;
        uSrc[u] = Wu + (size_t)bk * NS + n0 + bc * 4;
        bDst[u] = (uint32_t)((1536 + bk * 64 + cph * 4) * 4);
    }

    // fragment word offsets
    int aw[4];
    #pragma unroll
    for (int mi = 0; mi < 4; mi++)
        aw[mi] = (wm * 64 + mi * 16 + grp) * 12 + tg;
    int bwv[4];
    #pragma unroll
    for (int ni = 0; ni < 4; ni++) {
        int n = wn * 32 + ni * 8 + grp;
        int cph = (n >> 2) ^ (tg << 1);
        bwv[ni] = 1536 + tg * 128 + cph * 4 + (n & 3);
    }

    const int NC = H_DIM / 16;  // 64
    // prologue: stages 0, 1
    #pragma unroll
    for (int c = 0; c < 2; c++) {
        uint32_t st = sb + c * STAGE_B;
        #pragma unroll
        for (int u = 0; u < 2; u++) {
            CP16(st + aDst[u], aSrc[u] + c * 16, aSz[u]);
            CP16(st + bDst[u],        gSrc[u] + (size_t)c * 16 * NS, 16u);
            CP16(st + bDst[u] + 4096, uSrc[u] + (size_t)c * 16 * NS, 16u);
        }
        CP_COMMIT();
    }

    float cg[4][4][4], cu[4][4][4];
    #pragma unroll
    for (int mi = 0; mi < 4; mi++)
        #pragma unroll
        for (int ni = 0; ni < 4; ni++)
            #pragma unroll
            for (int q = 0; q < 4; q++) { cg[mi][ni][q] = 0.f; cu[mi][ni][q] = 0.f; }

    for (int c = 0; c < NC; c++) {
        CP_WAIT1();
        __syncthreads();
        if (c + 2 < NC) {
            int c2 = c + 2;
            uint32_t st = sb + (c2 % 3) * STAGE_B;
            #pragma unroll
            for (int u = 0; u < 2; u++) {
                CP16(st + aDst[u], aSrc[u] + c2 * 16, aSz[u]);
                CP16(st + bDst[u],        gSrc[u] + (size_t)c2 * 16 * NS, 16u);
                CP16(st + bDst[u] + 4096, uSrc[u] + (size_t)c2 * 16 * NS, 16u);
            }
        }
        CP_COMMIT();
        const uint32_t* S = sm + (c % 3) * STAGE_W;
        const float* Sf = (const float*)S;
        uint32_t af[4][4];
        #pragma unroll
        for (int mi = 0; mi < 4; mi++) {
            af[mi][0] = S[aw[mi]];
            af[mi][1] = S[aw[mi] + 96];
            af[mi][2] = S[aw[mi] + 4];
            af[mi][3] = S[aw[mi] + 100];
        }
        #pragma unroll
        for (int ni = 0; ni < 4; ni++) {
            const int w = bwv[ni];
            uint32_t bg0 = h2pack(Sf[w],        Sf[w + 64]);
            uint32_t bg1 = h2pack(Sf[w + 512],  Sf[w + 576]);
            uint32_t bu0 = h2pack(Sf[w + 1024], Sf[w + 1088]);
            uint32_t bu1 = h2pack(Sf[w + 1536], Sf[w + 1600]);
            #pragma unroll
            for (int mi = 0; mi < 4; mi++) {
                mma_f16(cg[mi][ni], af[mi][0], af[mi][1], af[mi][2], af[mi][3], bg0, bg1);
                mma_f16(cu[mi][ni], af[mi][0], af[mi][1], af[mi][2], af[mi][3], bu0, bu1);
            }
        }
    }

    // epilogue: silu(g)*u (* wgt), store fp16
    #pragma unroll
    for (int mi = 0; mi < 4; mi++) {
        int r0 = m0 + wm * 64 + mi * 16 + grp;
        int r1 = r0 + 8;
        float w0 = 1.f, w1 = 1.f;
        if (routed) {
            if (r0 < M) w0 = g_wgt[e * T_TOK + r0];
            if (r1 < M) w1 = g_wgt[e * T_TOK + r1];
        }
        #pragma unroll
        for (int ni = 0; ni < 4; ni++) {
            int col = n0 + wn * 32 + ni * 8 + tg * 2;
            if (r0 < M) {
                uint32_t v = h2pack(silu_f(cg[mi][ni][0]) * cu[mi][ni][0] * w0,
                                    silu_f(cg[mi][ni][1]) * cu[mi][ni][1] * w0);
                *(uint32_t*)(Act + (size_t)r0 * NS + col) = v;
            }
            if (r1 < M) {
                uint32_t v = h2pack(silu_f(cg[mi][ni][2]) * cu[mi][ni][2] * w1,
                                    silu_f(cg[mi][ni][3]) * cu[mi][ni][3] * w1);
                *(uint32_t*)(Act + (size_t)r1 * NS + col) = v;
            }
        }
    }
}

// ---------------------------------------------------------------------------
// Down-proj fp16 MMA: staged plain stores (no atomics)
// Block 128x128, BK=16, 4 warps (2m x 2n), warp 64x64.
// A: cp.async fp16 from act. B: cp.async fp32 -> cvt at read.
// z<32: routed expert z -> g_dact. z>=32: shared K-slice -> g_sds.
// ---------------------------------------------------------------------------
__global__ __launch_bounds__(128, 3)
void k_down(const float* __restrict__ w_down,
            const float* __restrict__ ws_down)
{
    extern __shared__ uint32_t sm[];
    const int z = blockIdx.z;
    const bool routed = z < E_NUM;
    const int e = routed ? z : 0;
    const int M = routed ? g_cnt[e] : T_TOK;
    const int m0 = blockIdx.y * 128;
    if (m0 >= M) return;
    const int n0 = blockIdx.x * 128;
    const int koff = routed ? 0 : (z - E_NUM) * 512;
    const __half* __restrict__ A = routed ? g_act + (size_t)e * T_TOK * I_DIM : g_sact;
    const int AS = routed ? I_DIM : IS_DIM;
    const float* __restrict__ B = routed ? w_down + (size_t)e * I_DIM * H_DIM
                                         : ws_down + (size_t)koff * H_DIM;
    float* __restrict__ Dst = routed ? g_dact + (size_t)e * T_TOK * H_DIM
                                     : g_sds[z - E_NUM];
    const int N = H_DIM;

    const uint32_t sb = smem_u32(sm);
    const int tid = threadIdx.x;
    const int warp = tid >> 5, lane = tid & 31;
    const int wm = warp & 1, wn = warp >> 1;
    const int grp = lane >> 2, tg = lane & 3;

    // A cp.async: 256 units, 2/thread
    const __half* aSrc[2];
    uint32_t aDst[2], aSz[2];
    #pragma unroll
    for (int u = 0; u < 2; u++) {
        int idx = tid + u * 128;
        int am = idx >> 1, ak = idx & 1;
        int gm = m0 + am;
        bool ok = gm < M;
        aSrc[u] = A + (size_t)(ok ? gm : 0) * AS + koff + ak * 8;
        aDst[u] = (uint32_t)(am * 48 + ak * 16);
        aSz[u] = ok ? 16u : 0u;
    }
    // B cp.async (fp32): 16 rows x 32 chunks = 512 units, 4/thread
    const float* bSrc[4];
    uint32_t bDst[4];
    #pragma unroll
    for (int u = 0; u < 4; u++) {
        int idx = tid + u * 128;
        int bk = idx >> 5, bc = idx & 31;
        int cph = bc ^ (((bk >> 1) & 3) << 1);
        bSrc[u] = B + (size_t)bk * N + n0 + bc * 4;
        bDst[u] = (uint32_t)((1536 + bk * 128 + cph * 4) * 4);
    }

    int aw[4];
    #pragma unroll
    for (int mi = 0; mi < 4; mi++)
        aw[mi] = (wm * 64 + mi * 16 + grp) * 12 + tg;
    int bwv[8];
    #pragma unroll
    for (int ni = 0; ni < 8; ni++) {
        int n = wn * 64 + ni * 8 + grp;
        int cph = (n >> 2) ^ (tg << 1);
        bwv[ni] = 1536 + tg * 256 + cph * 4 + (n & 3);
    }

    const int NC = 512 / 16;  // 32
    #pragma unroll
    for (int c = 0; c < 2; c++) {
        uint32_t st = sb + c * STAGE_B;
        #pragma unroll
        for (int u = 0; u < 2; u++) CP16(st + aDst[u], aSrc[u] + c * 16, aSz[u]);
        #pragma unroll
        for (int u = 0; u < 4; u++)
            CP16(st + bDst[u], bSrc[u] + (size_t)c * 16 * N, 16u);
        CP_COMMIT();
    }

    float acc[4][8][4];
    #pragma unroll
    for (int mi = 0; mi < 4; mi++)
        #pragma unroll
        for (int ni = 0; ni < 8; ni++)
            #pragma unroll
            for (int q = 0; q < 4; q++) acc[mi][ni][q] = 0.f;

    for (int c = 0; c < NC; c++) {
        CP_WAIT1();
        __syncthreads();
        if (c + 2 < NC) {
            int c2 = c + 2;
            uint32_t st = sb + (c2 % 3) * STAGE_B;
            #pragma unroll
            for (int u = 0; u < 2; u++) CP16(st + aDst[u], aSrc[u] + c2 * 16, aSz[u]);
            #pragma unroll
            for (int u = 0; u < 4; u++)
                CP16(st + bDst[u], bSrc[u] + (size_t)c2 * 16 * N, 16u);
        }
        CP_COMMIT();
        const uint32_t* S = sm + (c % 3) * STAGE_W;
        const float* Sf = (const float*)S;
        uint32_t af[4][4];
        #pragma unroll
        for (int mi = 0; mi < 4; mi++) {
            af[mi][0] = S[aw[mi]];
            af[mi][1] = S[aw[mi] + 96];
            af[mi][2] = S[aw[mi] + 4];
            af[mi][3] = S[aw[mi] + 100];
        }
        #pragma unroll
        for (int ni = 0; ni < 8; ni++) {
            const int w = bwv[ni];
            uint32_t b0 = h2pack(Sf[w],        Sf[w + 128]);
            uint32_t b1 = h2pack(Sf[w + 1024], Sf[w + 1152]);
            #pragma unroll
            for (int mi = 0; mi < 4; mi++)
                mma_f16(acc[mi][ni], af[mi][0], af[mi][1], af[mi][2], af[mi][3], b0, b1);
        }
    }

    // epilogue: plain stores to staging
    #pragma unroll
    for (int mi = 0; mi < 4; mi++) {
        int r0 = m0 + wm * 64 + mi * 16 + grp;
        int r1 = r0 + 8;
        bool ok0 = r0 < M, ok1 = r1 < M;
        #pragma unroll
        for (int ni = 0; ni < 8; ni++) {
            int col = n0 + wn * 64 + ni * 8 + tg * 2;
            if (ok0) {
                float2 v = make_float2(acc[mi][ni][0], acc[mi][ni][1]);
                *(float2*)(Dst + (size_t)r0 * N + col) = v;
            }
            if (ok1) {
                float2 v = make_float2(acc[mi][ni][2], acc[mi][ni][3]);
                *(float2*)(Dst + (size_t)r1 * N + col) = v;
            }
        }
    }
}

// ---------------------------------------------------------------------------
// Final gather-reduce: out[t] = sum_{i<8} g_dact[pos_i] + sum_{s<4} g_sds[s][t]
// ---------------------------------------------------------------------------
__global__ __launch_bounds__(256) void k_reduce(float* __restrict__ out) {
    __shared__ int pos[TOPK];
    const int t = blockIdx.x;
    if (threadIdx.x < TOPK) pos[threadIdx.x] = g_pos[t * TOPK + threadIdx.x];
    __syncthreads();
    const int h = threadIdx.x * 4;
    float4 s = *(const float4*)(&g_sds[0][(size_t)t * H_DIM + h]);
    #pragma unroll
    for (int q = 1; q < 4; q++) {
        float4 v = *(const float4*)(&g_sds[q][(size_t)t * H_DIM + h]);
        s.x += v.x; s.y += v.y; s.z += v.z; s.w += v.w;
    }
    #pragma unroll
    for (int i = 0; i < TOPK; i++) {
        float4 v = *(const float4*)(g_dact + (size_t)pos[i] * H_DIM + h);
        s.x += v.x; s.y += v.y; s.z += v.z; s.w += v.w;
    }
    *(float4*)(out + (size_t)t * H_DIM + h) = s;
}

// ---------------------------------------------------------------------------
extern "C" void kernel_launch(void* const* d_in, const int* in_sizes, int n_in,
                              void* d_out, int out_size)
{
    const float* x       = (const float*)d_in[0];
    const float* gate_w  = (const float*)d_in[1];
    const float* e_bias  = (const float*)d_in[2];
    const float* w_gate  = (const float*)d_in[3];
    const float* w_up    = (const float*)d_in[4];
    const float* w_down  = (const float*)d_in[5];
    const float* ws_gate = (const float*)d_in[6];
    const float* ws_up   = (const float*)d_in[7];
    const float* ws_down = (const float*)d_in[8];
    float* out = (float*)d_out;

    static bool attr_done = false;
    if (!attr_done) {
        cudaFuncSetAttribute(k_dual, cudaFuncAttributeMaxDynamicSharedMemorySize, SMEM_BYTES);
        cudaFuncSetAttribute(k_down, cudaFuncAttributeMaxDynamicSharedMemorySize, SMEM_BYTES);
        attr_done = true;
    }

    k_xtf<<<(T_TOK * H_DIM) / (256 * 4), 256>>>(x);
    k_gate_route<<<T_TOK, 256>>>(x, gate_w, e_bias);
    k_dual<<<dim3(8, 8, E_NUM + 4), 128, SMEM_BYTES>>>(w_gate, w_up, ws_gate, ws_up);
    k_down<<<dim3(8, 8, E_NUM + 4), 128, SMEM_BYTES>>>(w_down, ws_down);
    k_reduce<<<T_TOK, 256>>>(out);
}

// round 11
// speedup vs baseline: 1.6424x; 1.0278x over previous
#include <cuda_runtime.h>
#include <cuda_fp16.h>
#include <math.h>
#include <stdint.h>

#define T_TOK 1024
#define H_DIM 1024
#define E_NUM 32
#define I_DIM 512
#define IS_DIM 2048
#define NGROUP 8
#define GSIZE 4
#define TOPKG 4
#define TOPK 8
#define RSCALE 2.5f

// Scratch: activations stored as fp16
__device__ __half g_xh[(size_t)T_TOK * H_DIM];
__device__ __half g_act[(size_t)E_NUM * T_TOK * I_DIM];
__device__ __half g_sact[(size_t)T_TOK * IS_DIM];
__device__ float g_dact[(size_t)E_NUM * T_TOK * H_DIM];   // routed down staging
__device__ float g_sds[4][(size_t)T_TOK * H_DIM];         // shared split-K staging
__device__ int   g_cnt[E_NUM];
__device__ int   g_tok[E_NUM * T_TOK];
__device__ float g_wgt[E_NUM * T_TOK];
__device__ int   g_pos[T_TOK * TOPK];

__device__ __forceinline__ float silu_f(float v) { return v / (1.f + expf(-v)); }

__device__ __forceinline__ uint32_t h2pack(float a, float b) {
    __half2 h = __floats2half2_rn(a, b);
    return *reinterpret_cast<uint32_t*>(&h);
}

__device__ __forceinline__ uint32_t smem_u32(const void* p) {
    uint32_t a;
    asm("{ .reg .u64 t; cvta.to.shared.u64 t, %1; cvt.u32.u64 %0, t; }" : "=r"(a) : "l"(p));
    return a;
}

__device__ __forceinline__ void mma_f16(float* c,
                                        uint32_t a0, uint32_t a1, uint32_t a2, uint32_t a3,
                                        uint32_t b0, uint32_t b1)
{
    asm volatile(
        "mma.sync.aligned.m16n8k16.row.col.f32.f16.f16.f32 "
        "{%0,%1,%2,%3}, {%4,%5,%6,%7}, {%8,%9}, {%0,%1,%2,%3};\n"
        : "+f"(c[0]), "+f"(c[1]), "+f"(c[2]), "+f"(c[3])
        : "r"(a0), "r"(a1), "r"(a2), "r"(a3), "r"(b0), "r"(b1));
}

__device__ __forceinline__ void ldm_x4(uint32_t* r, uint32_t addr) {
    asm volatile("ldmatrix.sync.aligned.m8n8.x4.shared.b16 {%0,%1,%2,%3}, [%4];"
        : "=r"(r[0]), "=r"(r[1]), "=r"(r[2]), "=r"(r[3]) : "r"(addr));
}

#define CP16(dst, src, sz) \
    asm volatile("cp.async.cg.shared.global [%0], [%1], 16, %2;" \
                 :: "r"(dst), "l"(src), "r"(sz) : "memory")
#define CP_COMMIT() asm volatile("cp.async.commit_group;" ::: "memory")
#define CP_WAIT0()  asm volatile("cp.async.wait_group 0;" ::: "memory")

// convert X -> fp16 once; block 0 zeroes expert counters
__global__ void k_xtf(const float* __restrict__ x) {
    if (blockIdx.x == 0 && threadIdx.x < E_NUM) g_cnt[threadIdx.x] = 0;
    size_t i = (size_t)blockIdx.x * 256 + threadIdx.x;
    float4 v = ((const float4*)x)[i];
    ((uint2*)g_xh)[i] = make_uint2(h2pack(v.x, v.y), h2pack(v.z, v.w));
}

// ---------------------------------------------------------------------------
// Gate GEMV + DeepseekV3 noaux_tc routing + per-expert gather
// ---------------------------------------------------------------------------
__global__ __launch_bounds__(256) void k_gate_route(
    const float* __restrict__ x,
    const float* __restrict__ gate_w,
    const float* __restrict__ e_bias)
{
    __shared__ float s_logit[E_NUM];
    const int t = blockIdx.x;
    const int warp = threadIdx.x >> 5, lane = threadIdx.x & 31;
    const float* xr = x + (size_t)t * H_DIM;
    for (int e = warp; e < E_NUM; e += 8) {
        const float* gw = gate_w + (size_t)e * H_DIM;
        float s = 0.f;
        for (int k = lane; k < H_DIM; k += 32) s += xr[k] * gw[k];
        #pragma unroll
        for (int o = 16; o; o >>= 1) s += __shfl_xor_sync(0xffffffffu, s, o);
        if (lane == 0) s_logit[e] = s;
    }
    __syncthreads();
    if (threadIdx.x != 0) return;

    float scores[E_NUM], swb[E_NUM];
    for (int e = 0; e < E_NUM; e++) {
        float sc = 1.f / (1.f + expf(-s_logit[e]));
        scores[e] = sc;
        swb[e] = sc + e_bias[e];
    }
    float gs[NGROUP];
    for (int g = 0; g < NGROUP; g++) {
        float m1 = -1e30f, m2 = -1e30f;
        for (int j = 0; j < GSIZE; j++) {
            float v = swb[g * GSIZE + j];
            if (v > m1) { m2 = m1; m1 = v; }
            else if (v > m2) m2 = v;
        }
        gs[g] = m1 + m2;
    }
    bool gsel[NGROUP] = {false};
    for (int it = 0; it < TOPKG; it++) {
        int bi = 0; float bv = -1e30f;
        for (int g = 0; g < NGROUP; g++)
            if (!gsel[g] && gs[g] > bv) { bv = gs[g]; bi = g; }
        gsel[bi] = true;
    }
    float val[E_NUM];
    for (int e = 0; e < E_NUM; e++) val[e] = gsel[e / GSIZE] ? swb[e] : 0.f;
    bool taken[E_NUM] = {false};
    int sel[TOPK];
    float denom = 0.f;
    for (int it = 0; it < TOPK; it++) {
        int bi = 0; float bv = -1e30f;
        for (int e = 0; e < E_NUM; e++)
            if (!taken[e] && val[e] > bv) { bv = val[e]; bi = e; }
        taken[bi] = true; sel[it] = bi; denom += scores[bi];
    }
    float inv = RSCALE / (denom + 1e-20f);
    for (int it = 0; it < TOPK; it++) {
        int e = sel[it];
        int slot = atomicAdd(&g_cnt[e], 1);
        g_tok[e * T_TOK + slot] = t;
        g_wgt[e * T_TOK + slot] = scores[e] * inv;
        g_pos[t * TOPK + it] = e * T_TOK + slot;
    }
}

// ---------------------------------------------------------------------------
// Per-stage smem (32-bit words), BK=32:
//   A (fp16): 128 rows x 20 words (16 data + 4 pad) = 2560 w, base 0
//   B (fp32): [k][n], 32 rows, 16B-chunk swizzle phys = bc ^ (((bk>>1)&3)<<1)
//   dual: rowW=64, g @2560, u @4608; down: rowW=128 @2560 -> stage 6656 w
// Stage = 26624 B; 2 stages = 53248 B dynamic smem (3 CTAs/SM = 160 KB).
// ---------------------------------------------------------------------------
#define STAGE_W 6656
#define STAGE_B 26624
#define SMEM_BYTES (2 * STAGE_B)

// ---------------------------------------------------------------------------
// Dual fp16 MMA GEMM: act = silu(X@Wg)*(X@Wu) [* combine]  (fp32 acc)
// Block 128x64, BK=32, 4 warps (2m x 2n), warp 64x32 dual, ldmatrix A.
// z<32: routed expert z. z>=32: shared N-slice (z-32)*512.
// ---------------------------------------------------------------------------
__global__ __launch_bounds__(128, 3)
void k_dual(const float* __restrict__ w_gate,
            const float* __restrict__ w_up,
            const float* __restrict__ ws_gate,
            const float* __restrict__ ws_up)
{
    extern __shared__ uint32_t sm[];
    const int z = blockIdx.z;
    const bool routed = z < E_NUM;
    const int e = routed ? z : 0;
    const int M = routed ? g_cnt[e] : T_TOK;
    const int m0 = blockIdx.y * 128;
    if (m0 >= M) return;
    const int NS = routed ? I_DIM : IS_DIM;
    const int n0 = routed ? blockIdx.x * 64
                          : (z - E_NUM) * 512 + blockIdx.x * 64;
    const float* __restrict__ Wg = routed ? w_gate + (size_t)e * H_DIM * I_DIM : ws_gate;
    const float* __restrict__ Wu = routed ? w_up   + (size_t)e * H_DIM * I_DIM : ws_up;
    __half* __restrict__ Act = routed ? g_act + (size_t)e * T_TOK * I_DIM : g_sact;

    const uint32_t sb = smem_u32(sm);
    const int tid = threadIdx.x;
    const int warp = tid >> 5, lane = tid & 31;
    const int wm = warp & 1, wn = warp >> 1;
    const int grp = lane >> 2, tg = lane & 3;

    // A cp.async: 128 rows x 32 halves = 512 16B-units, 4/thread
    const __half* aSrc[4];
    uint32_t aDst[4], aSz[4];
    #pragma unroll
    for (int u = 0; u < 4; u++) {
        int idx = tid + u * 128;
        int am = idx >> 2, ak = idx & 3;
        int gm = m0 + am;
        bool ok = gm < M;
        int srow = ok ? (routed ? g_tok[e * T_TOK + gm] : gm) : 0;
        aSrc[u] = g_xh + (size_t)srow * H_DIM + ak * 8;
        aDst[u] = (uint32_t)(am * 80 + ak * 16);
        aSz[u] = ok ? 16u : 0u;
    }
    // B cp.async (fp32): per matrix 32 rows x 16 chunks = 512 units, 4/thr/mat
    const float* gSrc[4];
    const float* uSrc[4];
    uint32_t bDst[4];
    #pragma unroll
    for (int u = 0; u < 4; u++) {
        int idx = tid + u * 128;
        int bk = idx >> 4, bc = idx & 15;
        int cph = bc ^ (((bk >> 1) & 3) << 1);
        gSrc[u] = Wg + (size_t)bk * NS + n0 + bc * 4;
        uSrc[u] = Wu + (size_t)bk * NS + n0 + bc * 4;
        bDst[u] = (uint32_t)((2560 + bk * 64 + cph * 4) * 4);
    }

    // ldmatrix per-lane A row offsets (tiles: m0k0, m8k0, m0k8, m8k8)
    uint32_t lmoff[4];
    {
        int lr = (lane & 7) + ((lane >> 3) & 1) * 8;
        int lk = lane >> 4;
        #pragma unroll
        for (int mi = 0; mi < 4; mi++)
            lmoff[mi] = (uint32_t)((wm * 64 + mi * 16 + lr) * 80 + lk * 16);
    }
    // B fragment word offsets (rows 2tg/2tg+1 share swizzle phase)
    int bwv[4];
    #pragma unroll
    for (int ni = 0; ni < 4; ni++) {
        int n = wn * 32 + ni * 8 + grp;
        int cph = (n >> 2) ^ (tg << 1);
        bwv[ni] = 2560 + tg * 128 + cph * 4 + (n & 3);
    }

    const int NC = H_DIM / 32;  // 32
    // prologue: chunk 0 -> buf 0
    #pragma unroll
    for (int u = 0; u < 4; u++) {
        CP16(sb + aDst[u], aSrc[u], aSz[u]);
        CP16(sb + bDst[u],        gSrc[u], 16u);
        CP16(sb + bDst[u] + 8192, uSrc[u], 16u);
    }
    CP_COMMIT();

    float cg[4][4][4], cu[4][4][4];
    #pragma unroll
    for (int mi = 0; mi < 4; mi++)
        #pragma unroll
        for (int ni = 0; ni < 4; ni++)
            #pragma unroll
            for (int q = 0; q < 4; q++) { cg[mi][ni][q] = 0.f; cu[mi][ni][q] = 0.f; }

    for (int c = 0; c < NC; c++) {
        CP_WAIT0();
        __syncthreads();
        if (c + 1 < NC) {
            int c1 = c + 1;
            uint32_t st = sb + (c1 & 1) * STAGE_B;
            #pragma unroll
            for (int u = 0; u < 4; u++) {
                CP16(st + aDst[u], aSrc[u] + c1 * 32, aSz[u]);
                CP16(st + bDst[u],        gSrc[u] + (size_t)c1 * 32 * NS, 16u);
                CP16(st + bDst[u] + 8192, uSrc[u] + (size_t)c1 * 32 * NS, 16u);
            }
            CP_COMMIT();
        }
        const uint32_t sbase = sb + (c & 1) * STAGE_B;
        const float* Sf = (const float*)(sm + (c & 1) * STAGE_W);
        #pragma unroll
        for (int ks = 0; ks < 2; ks++) {
            uint32_t af[4][4];
            #pragma unroll
            for (int mi = 0; mi < 4; mi++)
                ldm_x4(af[mi], sbase + lmoff[mi] + ks * 32);
            #pragma unroll
            for (int ni = 0; ni < 4; ni++) {
                const int w = bwv[ni] + ks * 1024;
                uint32_t bg0 = h2pack(Sf[w],        Sf[w + 64]);
                uint32_t bg1 = h2pack(Sf[w + 512],  Sf[w + 576]);
                uint32_t bu0 = h2pack(Sf[w + 2048], Sf[w + 2112]);
                uint32_t bu1 = h2pack(Sf[w + 2560], Sf[w + 2624]);
                #pragma unroll
                for (int mi = 0; mi < 4; mi++) {
                    mma_f16(cg[mi][ni], af[mi][0], af[mi][1], af[mi][2], af[mi][3], bg0, bg1);
                    mma_f16(cu[mi][ni], af[mi][0], af[mi][1], af[mi][2], af[mi][3], bu0, bu1);
                }
            }
        }
    }

    // epilogue: silu(g)*u (* wgt), store fp16
    #pragma unroll
    for (int mi = 0; mi < 4; mi++) {
        int r0 = m0 + wm * 64 + mi * 16 + grp;
        int r1 = r0 + 8;
        float w0 = 1.f, w1 = 1.f;
        if (routed) {
            if (r0 < M) w0 = g_wgt[e * T_TOK + r0];
            if (r1 < M) w1 = g_wgt[e * T_TOK + r1];
        }
        #pragma unroll
        for (int ni = 0; ni < 4; ni++) {
            int col = n0 + wn * 32 + ni * 8 + tg * 2;
            if (r0 < M) {
                uint32_t v = h2pack(silu_f(cg[mi][ni][0]) * cu[mi][ni][0] * w0,
                                    silu_f(cg[mi][ni][1]) * cu[mi][ni][1] * w0);
                *(uint32_t*)(Act + (size_t)r0 * NS + col) = v;
            }
            if (r1 < M) {
                uint32_t v = h2pack(silu_f(cg[mi][ni][2]) * cu[mi][ni][2] * w1,
                                    silu_f(cg[mi][ni][3]) * cu[mi][ni][3] * w1);
                *(uint32_t*)(Act + (size_t)r1 * NS + col) = v;
            }
        }
    }
}

// ---------------------------------------------------------------------------
// Down-proj fp16 MMA: staged plain stores (no atomics)
// Block 128x128, BK=32, 4 warps (2m x 2n), warp 64x64, ldmatrix A.
// z<32: routed expert z -> g_dact. z>=32: shared K-slice -> g_sds.
// ---------------------------------------------------------------------------
__global__ __launch_bounds__(128, 3)
void k_down(const float* __restrict__ w_down,
            const float* __restrict__ ws_down)
{
    extern __shared__ uint32_t sm[];
    const int z = blockIdx.z;
    const bool routed = z < E_NUM;
    const int e = routed ? z : 0;
    const int M = routed ? g_cnt[e] : T_TOK;
    const int m0 = blockIdx.y * 128;
    if (m0 >= M) return;
    const int n0 = blockIdx.x * 128;
    const int koff = routed ? 0 : (z - E_NUM) * 512;
    const __half* __restrict__ A = routed ? g_act + (size_t)e * T_TOK * I_DIM : g_sact;
    const int AS = routed ? I_DIM : IS_DIM;
    const float* __restrict__ B = routed ? w_down + (size_t)e * I_DIM * H_DIM
                                         : ws_down + (size_t)koff * H_DIM;
    float* __restrict__ Dst = routed ? g_dact + (size_t)e * T_TOK * H_DIM
                                     : g_sds[z - E_NUM];
    const int N = H_DIM;

    const uint32_t sb = smem_u32(sm);
    const int tid = threadIdx.x;
    const int warp = tid >> 5, lane = tid & 31;
    const int wm = warp & 1, wn = warp >> 1;
    const int grp = lane >> 2, tg = lane & 3;

    // A cp.async: 512 units, 4/thread
    const __half* aSrc[4];
    uint32_t aDst[4], aSz[4];
    #pragma unroll
    for (int u = 0; u < 4; u++) {
        int idx = tid + u * 128;
        int am = idx >> 2, ak = idx & 3;
        int gm = m0 + am;
        bool ok = gm < M;
        aSrc[u] = A + (size_t)(ok ? gm : 0) * AS + koff + ak * 8;
        aDst[u] = (uint32_t)(am * 80 + ak * 16);
        aSz[u] = ok ? 16u : 0u;
    }
    // B cp.async (fp32): 32 rows x 32 chunks = 1024 units, 8/thread
    const float* bSrc[8];
    uint32_t bDst[8];
    #pragma unroll
    for (int u = 0; u < 8; u++) {
        int idx = tid + u * 128;
        int bk = idx >> 5, bc = idx & 31;
        int cph = bc ^ (((bk >> 1) & 3) << 1);
        bSrc[u] = B + (size_t)bk * N + n0 + bc * 4;
        bDst[u] = (uint32_t)((2560 + bk * 128 + cph * 4) * 4);
    }

    uint32_t lmoff[4];
    {
        int lr = (lane & 7) + ((lane >> 3) & 1) * 8;
        int lk = lane >> 4;
        #pragma unroll
        for (int mi = 0; mi < 4; mi++)
            lmoff[mi] = (uint32_t)((wm * 64 + mi * 16 + lr) * 80 + lk * 16);
    }
    int bwv[8];
    #pragma unroll
    for (int ni = 0; ni < 8; ni++) {
        int n = wn * 64 + ni * 8 + grp;
        int cph = (n >> 2) ^ (tg << 1);
        bwv[ni] = 2560 + tg * 256 + cph * 4 + (n & 3);
    }

    const int NC = 512 / 32;  // 16
    #pragma unroll
    for (int u = 0; u < 4; u++) CP16(sb + aDst[u], aSrc[u], aSz[u]);
    #pragma unroll
    for (int u = 0; u < 8; u++) CP16(sb + bDst[u], bSrc[u], 16u);
    CP_COMMIT();

    float acc[4][8][4];
    #pragma unroll
    for (int mi = 0; mi < 4; mi++)
        #pragma unroll
        for (int ni = 0; ni < 8; ni++)
            #pragma unroll
            for (int q = 0; q < 4; q++) acc[mi][ni][q] = 0.f;

    for (int c = 0; c < NC; c++) {
        CP_WAIT0();
        __syncthreads();
        if (c + 1 < NC) {
            int c1 = c + 1;
            uint32_t st = sb + (c1 & 1) * STAGE_B;
            #pragma unroll
            for (int u = 0; u < 4; u++) CP16(st + aDst[u], aSrc[u] + c1 * 32, aSz[u]);
            #pragma unroll
            for (int u = 0; u < 8; u++)
                CP16(st + bDst[u], bSrc[u] + (size_t)c1 * 32 * N, 16u);
            CP_COMMIT();
        }
        const uint32_t sbase = sb + (c & 1) * STAGE_B;
        const float* Sf = (const float*)(sm + (c & 1) * STAGE_W);
        #pragma unroll
        for (int ks = 0; ks < 2; ks++) {
            uint32_t af[4][4];
            #pragma unroll
            for (int mi = 0; mi < 4; mi++)
                ldm_x4(af[mi], sbase + lmoff[mi] + ks * 32);
            #pragma unroll
            for (int ni = 0; ni < 8; ni++) {
                const int w = bwv[ni] + ks * 2048;
                uint32_t b0 = h2pack(Sf[w],        Sf[w + 128]);
                uint32_t b1 = h2pack(Sf[w + 1024], Sf[w + 1152]);
                #pragma unroll
                for (int mi = 0; mi < 4; mi++)
                    mma_f16(acc[mi][ni], af[mi][0], af[mi][1], af[mi][2], af[mi][3], b0, b1);
            }
        }
    }

    // epilogue: plain stores to staging
    #pragma unroll
    for (int mi = 0; mi < 4; mi++) {
        int r0 = m0 + wm * 64 + mi * 16 + grp;
        int r1 = r0 + 8;
        bool ok0 = r0 < M, ok1 = r1 < M;
        #pragma unroll
        for (int ni = 0; ni < 8; ni++) {
            int col = n0 + wn * 64 + ni * 8 + tg * 2;
            if (ok0) {
                float2 v = make_float2(acc[mi][ni][0], acc[mi][ni][1]);
                *(float2*)(Dst + (size_t)r0 * N + col) = v;
            }
            if (ok1) {
                float2 v = make_float2(acc[mi][ni][2], acc[mi][ni][3]);
                *(float2*)(Dst + (size_t)r1 * N + col) = v;
            }
        }
    }
}

// ---------------------------------------------------------------------------
// Final gather-reduce: out[t] = sum_{i<8} g_dact[pos_i] + sum_{s<4} g_sds[s][t]
// ---------------------------------------------------------------------------
__global__ __launch_bounds__(256) void k_reduce(float* __restrict__ out) {
    __shared__ int pos[TOPK];
    const int t = blockIdx.x;
    if (threadIdx.x < TOPK) pos[threadIdx.x] = g_pos[t * TOPK + threadIdx.x];
    __syncthreads();
    const int h = threadIdx.x * 4;
    float4 s = *(const float4*)(&g_sds[0][(size_t)t * H_DIM + h]);
    #pragma unroll
    for (int q = 1; q < 4; q++) {
        float4 v = *(const float4*)(&g_sds[q][(size_t)t * H_DIM + h]);
        s.x += v.x; s.y += v.y; s.z += v.z; s.w += v.w;
    }
    #pragma unroll
    for (int i = 0; i < TOPK; i++) {
        float4 v = *(const float4*)(g_dact + (size_t)pos[i] * H_DIM + h);
        s.x += v.x; s.y += v.y; s.z += v.z; s.w += v.w;
    }
    *(float4*)(out + (size_t)t * H_DIM + h) = s;
}

// ---------------------------------------------------------------------------
extern "C" void kernel_launch(void* const* d_in, const int* in_sizes, int n_in,
                              void* d_out, int out_size)
{
    const float* x       = (const float*)d_in[0];
    const float* gate_w  = (const float*)d_in[1];
    const float* e_bias  = (const float*)d_in[2];
    const float* w_gate  = (const float*)d_in[3];
    const float* w_up    = (const float*)d_in[4];
    const float* w_down  = (const float*)d_in[5];
    const float* ws_gate = (const float*)d_in[6];
    const float* ws_up   = (const float*)d_in[7];
    const float* ws_down = (const float*)d_in[8];
    float* out = (float*)d_out;

    static bool attr_done = false;
    if (!attr_done) {
        cudaFuncSetAttribute(k_dual, cudaFuncAttributeMaxDynamicSharedMemorySize, SMEM_BYTES);
        cudaFuncSetAttribute(k_down, cudaFuncAttributeMaxDynamicSharedMemorySize, SMEM_BYTES);
        attr_done = true;
    }

    k_xtf<<<(T_TOK * H_DIM) / (256 * 4), 256>>>(x);
    k_gate_route<<<T_TOK, 256>>>(x, gate_w, e_bias);
    k_dual<<<dim3(8, 8, E_NUM + 4), 128, SMEM_BYTES>>>(w_gate, w_up, ws_gate, ws_up);
    k_down<<<dim3(8, 8, E_NUM + 4), 128, SMEM_BYTES>>>(w_down, ws_down);
    k_reduce<<<T_TOK, 256>>>(out);
}